// round 14
// baseline (speedup 1.0000x reference)
#include <cuda_runtime.h>
#include <cuda_fp16.h>
#include <cstdint>

// ---------------------------------------------------------------------------
// GIN 2-layer forward on GB300 (sm_103 target - no tcgen05 in toolchain).
// k_prep (cvt + weight transpose + zeroing) -> k_csr (count/scan/scatter in
// one kernel via grid barriers) -> warp-per-node fp16 gather aggregation ->
// fp16 mma.sync m16n8k16 GEMMs (ldmatrix, 3-stage cp.async, BK=64,
// 128x128 CTA / 64x32 warp tiles, 2 CTAs/SM, fused bias+ReLU).
// GEMM1 is the 4th launch (ncu profile target).
// ---------------------------------------------------------------------------

#define N_MAX 100000
#define E_MAX 1600000
#define CSR_NB 512

__device__ int    g_rowptr[N_MAX + 1];
__device__ int    g_cur[N_MAX];
__device__ int    g_colidx[E_MAX];
__device__ int    g_cnt[N_MAX];
__device__ int    g_bsum[128];
__device__ volatile int g_bar[8];
__device__ __half g_xh[(size_t)N_MAX * 256];
__device__ __half g_h0[(size_t)N_MAX * 256];
__device__ __half g_h1[(size_t)N_MAX * 512];
__device__ __half g_h2[(size_t)N_MAX * 512];
__device__ __half g_g2[(size_t)N_MAX * 512];
// weights transposed to [N][K], fp16
__device__ __half g_w1a[512 * 256];
__device__ __half g_w1b[512 * 512];
__device__ __half g_w2a[512 * 512];
__device__ __half g_w2b[256 * 512];

// ------------------------------- helpers -----------------------------------

__device__ __forceinline__ uint32_t smem_u32(const void* p) {
    uint32_t a;
    asm("{ .reg .u64 t; cvta.to.shared.u64 t, %1; cvt.u32.u64 %0, t; }"
        : "=r"(a) : "l"(p));
    return a;
}
__device__ __forceinline__ void cp16(uint32_t dst, const void* src, int srcsize) {
    asm volatile("cp.async.cg.shared.global [%0], [%1], 16, %2;"
                 :: "r"(dst), "l"(src), "r"(srcsize) : "memory");
}
#define CP_COMMIT() asm volatile("cp.async.commit_group;" ::: "memory")
#define CP_WAIT(n)  asm volatile("cp.async.wait_group %0;" :: "n"(n) : "memory")

__device__ __forceinline__ void mma_f16(float c[4], const uint32_t a[4],
                                        const uint32_t b0, const uint32_t b1) {
    asm volatile(
        "mma.sync.aligned.m16n8k16.row.col.f32.f16.f16.f32 "
        "{%0,%1,%2,%3}, {%4,%5,%6,%7}, {%8,%9}, {%0,%1,%2,%3};"
        : "+f"(c[0]), "+f"(c[1]), "+f"(c[2]), "+f"(c[3])
        : "r"(a[0]), "r"(a[1]), "r"(a[2]), "r"(a[3]), "r"(b0), "r"(b1));
}
__device__ __forceinline__ void ldsm4(uint32_t r[4], uint32_t addr) {
    asm volatile("ldmatrix.sync.aligned.m8n8.x4.shared.b16 {%0,%1,%2,%3}, [%4];"
                 : "=r"(r[0]), "=r"(r[1]), "=r"(r[2]), "=r"(r[3]) : "r"(addr));
}

// Per-block int64-layout detection: all blocks sample the same 256 odd words
// (deterministic, L2-hot). int64 little-endian with values < n  =>  all zero.
__device__ __forceinline__ int detect_is64(const int* __restrict__ ei32) {
    int p = (ei32[2 * (threadIdx.x & 255) + 1] != 0);
    return __syncthreads_or(p) ? 0 : 1;
}

// Grid-wide barrier: all CSR_NB blocks guaranteed co-resident (512 << limit).
__device__ __forceinline__ void gbar(int i) {
    __syncthreads();
    if (threadIdx.x == 0) {
        __threadfence();
        atomicAdd((int*)&g_bar[i], 1);
        while (g_bar[i] < CSR_NB) {}
    }
    __syncthreads();
}

// ------------------------------ k_prep (launch 1) ---------------------------
// Blocks [0, cvtBlocks): zero cnt/bars + convert x -> fp16.
// Blocks [cvtBlocks, cvtBlocks+768): 32x32 tile weight transposes (fp16 out).

__global__ void __launch_bounds__(256)
k_prep(const float4* __restrict__ X, __half2* __restrict__ Y, int n4,
       int* __restrict__ cnt, int n, int cvtBlocks,
       const float* __restrict__ W1a, const float* __restrict__ W1b,
       const float* __restrict__ W2a, const float* __restrict__ W2b,
       __half* __restrict__ o1a, __half* __restrict__ o1b,
       __half* __restrict__ o2a, __half* __restrict__ o2b) {
    __shared__ float tt[32][33];
    int bid = blockIdx.x, tid = threadIdx.x;
    if (bid < cvtBlocks) {
        int i = bid * 256 + tid;
        if (i < n) cnt[i] = 0;
        if (bid == 0 && tid < 8) g_bar[tid] = 0;
        if (i < n4) {
            float4 v = X[i];
            Y[2 * i] = __floats2half2_rn(v.x, v.y);
            Y[2 * i + 1] = __floats2half2_rn(v.z, v.w);
        }
    } else {
        int tl = bid - cvtBlocks;
        const float* W;
        __half* Wt;
        int K, N, t0;
        if (tl < 128)      { W = W1a; Wt = o1a; K = 256; N = 512; t0 = tl; }
        else if (tl < 384) { W = W1b; Wt = o1b; K = 512; N = 512; t0 = tl - 128; }
        else if (tl < 640) { W = W2a; Wt = o2a; K = 512; N = 512; t0 = tl - 384; }
        else               { W = W2b; Wt = o2b; K = 512; N = 256; t0 = tl - 640; }
        int nx = N / 32;
        int k0 = (t0 / nx) * 32, n0 = (t0 % nx) * 32;
        int tx = tid & 31, ty = tid >> 5;
#pragma unroll
        for (int r = ty; r < 32; r += 8)
            tt[r][tx] = W[(size_t)(k0 + r) * N + n0 + tx];
        __syncthreads();
#pragma unroll
        for (int r = ty; r < 32; r += 8)
            Wt[(size_t)(n0 + r) * K + k0 + tx] = __float2half_rn(tt[tx][r]);
    }
}

// ------------------------------ k_csr (launch 2) ----------------------------
// count -> scan -> scatter in one kernel via grid-wide barriers.

__global__ void __launch_bounds__(256)
k_csr(const int* __restrict__ ei32, int E, int n,
      int* __restrict__ cnt, int* __restrict__ rowptr, int* __restrict__ cur,
      int* __restrict__ colidx, int* __restrict__ bsum) {
    int is64 = detect_is64(ei32);
    int tid = threadIdx.x, b = blockIdx.x;
    int gsz = gridDim.x * blockDim.x;
    int gtid = b * 256 + tid;

    // ---- phase 1: count ----
    for (int e = gtid; e < E; e += gsz) {
        int d = is64 ? ei32[2 * E + 2 * e] : ei32[E + e];
        if (d < 0) d = 0; if (d >= n) d = n - 1;
        atomicAdd(&cnt[d], 1);
    }
    gbar(0);

    // ---- phase 2: local scans (1024 cnt entries per block) ----
    __shared__ int sh[256];
    __shared__ int sh2[128];
    int ntiles = (n + 1023) >> 10;
    int v[4];
    int ts = 0;
    int base = b * 1024 + tid * 4;
    if (b < ntiles) {
#pragma unroll
        for (int q = 0; q < 4; q++) v[q] = (base + q < n) ? cnt[base + q] : 0;
        ts = v[0] + v[1] + v[2] + v[3];
        sh[tid] = ts;
        __syncthreads();
        for (int off = 1; off < 256; off <<= 1) {
            int u = 0;
            if (tid >= off) u = sh[tid - off];
            __syncthreads();
            if (tid >= off) sh[tid] += u;
            __syncthreads();
        }
        if (tid == 255) bsum[b] = sh[255];
    }
    gbar(1);

    // ---- phase 3: top-level exclusive scan of block sums (block 0) ----
    if (b == 0 && tid < 128) {
        int val = (tid < ntiles) ? bsum[tid] : 0;
        sh2[tid] = val;
        __syncthreads();
        for (int off = 1; off < 128; off <<= 1) {
            int u = 0;
            if (tid >= off) u = sh2[tid - off];
            __syncthreads();
            if (tid >= off) sh2[tid] += u;
            __syncthreads();
        }
        if (tid < ntiles) bsum[tid] = sh2[tid] - val;
        if (tid == 127) rowptr[n] = sh2[127];
    } else if (b == 0) {
        // threads 128..255 must participate in the __syncthreads above
        __syncthreads();
        for (int off = 1; off < 128; off <<= 1) {
            __syncthreads();
            __syncthreads();
        }
    }
    gbar(2);

    // ---- phase 4: write rowptr + cursor copy ----
    if (b < ntiles) {
        int run = sh[tid] - ts + bsum[b];
#pragma unroll
        for (int q = 0; q < 4; q++) {
            if (base + q < n) { rowptr[base + q] = run; cur[base + q] = run; }
            run += v[q];
        }
    }
    gbar(3);

    // ---- phase 5: scatter ----
    for (int e = gtid; e < E; e += gsz) {
        int s, d;
        if (is64) {
            s = ei32[2 * e];
            d = ei32[2 * E + 2 * e];
        } else {
            s = ei32[e];
            d = ei32[E + e];
        }
        if (s < 0) s = 0; if (s >= n) s = n - 1;
        if (d < 0) d = 0; if (d >= n) d = n - 1;
        int pos = atomicAdd(&cur[d], 1);
        if (pos >= 0 && pos < E) colidx[pos] = s;
    }
}

// ------------------------------ aggregation -------------------------------
// Warp per node. Lane holds U4 uint4 (8 halfs each). fp32 accumulation,
// fp16 output. U4=1 -> F=256, U4=2 -> F=512. 3-edge unrolled gather.

template <int U4>
__global__ void __launch_bounds__(256)
k_agg_h(const uint4* __restrict__ X, uint4* __restrict__ Y,
        const int* __restrict__ rowptr, const int* __restrict__ colidx,
        const float* __restrict__ epsp, int n) {
    int warp = (blockIdx.x * blockDim.x + threadIdx.x) >> 5;
    if (warp >= n) return;
    int lane = threadIdx.x & 31;
    float sc = 1.0f + epsp[0];
    const int rowU = 32 * U4;
    size_t base = (size_t)warp * rowU + lane;

    float acc[U4][8];
#pragma unroll
    for (int u = 0; u < U4; u++) {
        uint4 v = __ldg(&X[base + u * 32]);
        const __half2* hp = (const __half2*)&v;
#pragma unroll
        for (int q = 0; q < 4; q++) {
            float2 f = __half22float2(hp[q]);
            acc[u][2 * q] = sc * f.x;
            acc[u][2 * q + 1] = sc * f.y;
        }
    }

    int beg = rowptr[warp];
    int end = rowptr[warp + 1];
    int j = beg;
    for (; j + 2 < end; j += 3) {
        int r0 = __ldg(&colidx[j]);
        int r1 = __ldg(&colidx[j + 1]);
        int r2 = __ldg(&colidx[j + 2]);
#pragma unroll
        for (int u = 0; u < U4; u++) {
            uint4 v0 = __ldg(&X[(size_t)r0 * rowU + lane + u * 32]);
            uint4 v1 = __ldg(&X[(size_t)r1 * rowU + lane + u * 32]);
            uint4 v2 = __ldg(&X[(size_t)r2 * rowU + lane + u * 32]);
            const __half2* h0 = (const __half2*)&v0;
            const __half2* h1 = (const __half2*)&v1;
            const __half2* h2 = (const __half2*)&v2;
#pragma unroll
            for (int q = 0; q < 4; q++) {
                float2 f0 = __half22float2(h0[q]);
                float2 f1 = __half22float2(h1[q]);
                float2 f2 = __half22float2(h2[q]);
                acc[u][2 * q] += f0.x + f1.x + f2.x;
                acc[u][2 * q + 1] += f0.y + f1.y + f2.y;
            }
        }
    }
    for (; j < end; j++) {
        int r0 = __ldg(&colidx[j]);
#pragma unroll
        for (int u = 0; u < U4; u++) {
            uint4 v0 = __ldg(&X[(size_t)r0 * rowU + lane + u * 32]);
            const __half2* h0 = (const __half2*)&v0;
#pragma unroll
            for (int q = 0; q < 4; q++) {
                float2 f0 = __half22float2(h0[q]);
                acc[u][2 * q] += f0.x;
                acc[u][2 * q + 1] += f0.y;
            }
        }
    }

#pragma unroll
    for (int u = 0; u < U4; u++) {
        uint4 o;
        __half2* op = (__half2*)&o;
#pragma unroll
        for (int q = 0; q < 4; q++)
            op[q] = __floats2half2_rn(acc[u][2 * q], acc[u][2 * q + 1]);
        Y[base + u * 32] = o;
    }
}

// --------------------------- fp16 mma.sync GEMM ----------------------------
// C = act(A[M,K] @ Wt[N,K]^T + bias). BM=BN=128, BK=64, 256 thr = 8 warps,
// warp tile 64x32, mma m16n8k16, ldmatrix.x4. 3-stage cp.async, 2 CTAs/SM.
// smem A: [m][k] halfs stride 72; smem B: [n][k] halfs stride 72.

#define A_B 18432
#define STG_B 36864              // bytes per stage (A 18432 + B 18432)
#define GSM_BYTES (3 * STG_B)    // 110592

template <bool RELU, bool OUTH>
__global__ void __launch_bounds__(256, 2)
k_gemm_h(const __half* __restrict__ A, const __half* __restrict__ B,
         const float* __restrict__ bias, void* __restrict__ Cv,
         int M, int K, int N) {
    extern __shared__ __align__(16) char smem[];
    const uint32_t sb = smem_u32(smem);

    const int tid = threadIdx.x;
    const int lane = tid & 31;
    const int w = tid >> 5;
    const int gid = lane >> 2;
    const int tig = lane & 3;
    const int wr = (w >> 2) * 64;
    const int wc = (w & 3) * 32;
    const int blockRow = blockIdx.y * 128;
    const int blockCol = blockIdx.x * 128;
    const int nch = K >> 6;

    const int quad = lane >> 3;
    const int qr = lane & 7;
    uint32_t aoff[4], boff[2];
#pragma unroll
    for (int ii = 0; ii < 4; ii++)
        aoff[ii] = ((wr + ii * 16 + (quad & 1) * 8 + qr) * 72 + (quad >> 1) * 8) * 2;
#pragma unroll
    for (int jp = 0; jp < 2; jp++)
        boff[jp] = ((wc + jp * 16 + (quad >> 1) * 8 + qr) * 72 + (quad & 1) * 8) * 2
                   + A_B;

    float c[4][4][4];
#pragma unroll
    for (int i = 0; i < 4; i++)
#pragma unroll
        for (int j = 0; j < 4; j++)
#pragma unroll
            for (int q = 0; q < 4; q++) c[i][j][q] = 0.0f;

#define ISSUE(ci, bf)                                                          \
    {                                                                          \
        uint32_t pa = sb + (bf) * STG_B;                                       \
        uint32_t pb = pa + A_B;                                                \
        int KT = (ci) << 6;                                                    \
        _Pragma("unroll") for (int t = 0; t < 4; t++) {                        \
            int cidx = tid + t * 256;                                          \
            int row = cidx >> 3, q = cidx & 7;                                 \
            int grow = blockRow + row;                                         \
            cp16(pa + row * 144 + q * 16,                                      \
                 &A[(size_t)grow * K + KT + q * 8], grow < M ? 16 : 0);        \
        }                                                                      \
        _Pragma("unroll") for (int t = 0; t < 4; t++) {                        \
            int cidx = tid + t * 256;                                          \
            int row = cidx >> 3, q = cidx & 7;                                 \
            cp16(pb + row * 144 + q * 16,                                      \
                 &B[(size_t)(blockCol + row) * K + KT + q * 8], 16);           \
        }                                                                      \
        CP_COMMIT();                                                           \
    }

    ISSUE(0, 0);
    if (nch > 1) ISSUE(1, 1);

    for (int i = 0; i < nch; i++) {
        if (i + 2 <= nch) { CP_WAIT(1); } else { CP_WAIT(0); }
        __syncthreads();

        if (i + 2 < nch) ISSUE(i + 2, (i + 2) % 3);

        uint32_t base = sb + (i % 3) * STG_B;
#pragma unroll
        for (int ks = 0; ks < 4; ks++) {
            uint32_t kboff = ks * 32;  // 16 halfs
            uint32_t a[4][4], b[2][4];
#pragma unroll
            for (int ii = 0; ii < 4; ii++) ldsm4(a[ii], base + aoff[ii] + kboff);
#pragma unroll
            for (int jp = 0; jp < 2; jp++) ldsm4(b[jp], base + boff[jp] + kboff);
#pragma unroll
            for (int ii = 0; ii < 4; ii++) {
                mma_f16(c[ii][0], a[ii], b[0][0], b[0][1]);
                mma_f16(c[ii][1], a[ii], b[0][2], b[0][3]);
                mma_f16(c[ii][2], a[ii], b[1][0], b[1][1]);
                mma_f16(c[ii][3], a[ii], b[1][2], b[1][3]);
            }
        }
    }

    // epilogue
#pragma unroll
    for (int j = 0; j < 4; j++) {
        int n0 = blockCol + wc + j * 8 + 2 * tig;
        float bb0 = bias[n0];
        float bb1 = bias[n0 + 1];
#pragma unroll
        for (int i = 0; i < 4; i++) {
            int m = blockRow + wr + i * 16 + gid;
            float v0 = c[i][j][0] + bb0;
            float v1 = c[i][j][1] + bb1;
            float v2 = c[i][j][2] + bb0;
            float v3 = c[i][j][3] + bb1;
            if (RELU) {
                v0 = fmaxf(v0, 0.f); v1 = fmaxf(v1, 0.f);
                v2 = fmaxf(v2, 0.f); v3 = fmaxf(v3, 0.f);
            }
            if (OUTH) {
                __half2* Ch = (__half2*)Cv;
                if (m < M) Ch[(size_t)m * (N >> 1) + (n0 >> 1)] = __floats2half2_rn(v0, v1);
                if (m + 8 < M)
                    Ch[(size_t)(m + 8) * (N >> 1) + (n0 >> 1)] = __floats2half2_rn(v2, v3);
            } else {
                float* Cf = (float*)Cv;
                if (m < M) *(float2*)&Cf[(size_t)m * N + n0] = make_float2(v0, v1);
                if (m + 8 < M)
                    *(float2*)&Cf[(size_t)(m + 8) * N + n0] = make_float2(v2, v3);
            }
        }
    }
#undef ISSUE
}

// ------------------------------ launcher -----------------------------------

extern "C" void kernel_launch(void* const* d_in, const int* in_sizes, int n_in,
                              void* d_out, int out_size) {
    const float* x    = (const float*)d_in[0];
    const int*   ei   = (const int*)d_in[1];
    const float* W1a  = (const float*)d_in[2];
    const float* b1a  = (const float*)d_in[3];
    const float* W1b  = (const float*)d_in[4];
    const float* b1b  = (const float*)d_in[5];
    const float* W2a  = (const float*)d_in[6];
    const float* b2a  = (const float*)d_in[7];
    const float* W2b  = (const float*)d_in[8];
    const float* b2b  = (const float*)d_in[9];
    const float* eps1 = (const float*)d_in[10];
    const float* eps2 = (const float*)d_in[11];
    float*       out  = (float*)d_out;

    int n = in_sizes[0] / 256;  // 100000 nodes
    int E = in_sizes[1] / 2;    // 1600000 edges

    int *rowptr, *cur, *colidx, *cnt, *bsum;
    __half *xh, *h0, *h1, *h2, *g2, *w1a, *w1b, *w2a, *w2b;
    cudaGetSymbolAddress((void**)&rowptr, g_rowptr);
    cudaGetSymbolAddress((void**)&cur, g_cur);
    cudaGetSymbolAddress((void**)&colidx, g_colidx);
    cudaGetSymbolAddress((void**)&cnt, g_cnt);
    cudaGetSymbolAddress((void**)&bsum, g_bsum);
    cudaGetSymbolAddress((void**)&xh, g_xh);
    cudaGetSymbolAddress((void**)&h0, g_h0);
    cudaGetSymbolAddress((void**)&h1, g_h1);
    cudaGetSymbolAddress((void**)&h2, g_h2);
    cudaGetSymbolAddress((void**)&g2, g_g2);
    cudaGetSymbolAddress((void**)&w1a, g_w1a);
    cudaGetSymbolAddress((void**)&w1b, g_w1b);
    cudaGetSymbolAddress((void**)&w2a, g_w2a);
    cudaGetSymbolAddress((void**)&w2b, g_w2b);

    cudaFuncSetAttribute(k_gemm_h<true, true>,
                         cudaFuncAttributeMaxDynamicSharedMemorySize, GSM_BYTES);
    cudaFuncSetAttribute(k_gemm_h<false, false>,
                         cudaFuncAttributeMaxDynamicSharedMemorySize, GSM_BYTES);

    int n4 = n * 64;                      // float4 count of x
    int cvtBlocks = (n4 + 255) / 256;     // 25000
    int prepBlocks = cvtBlocks + 768;     // + weight-transpose tiles

    // 1) prep: zero cnt/bars + x->fp16 + all weight transposes
    k_prep<<<prepBlocks, 256>>>((const float4*)x, (__half2*)xh, n4, cnt, n,
                                cvtBlocks, W1a, W1b, W2a, W2b,
                                w1a, w1b, w2a, w2b);

    // 2) CSR: count -> scan -> scatter (grid-barrier fused)
    k_csr<<<CSR_NB, 256>>>(ei, E, n, cnt, rowptr, cur, colidx, bsum);

    int mtiles = (n + 127) / 128;
    int ab = (n + 7) / 8;

    // 3) Layer-1 aggregation
    k_agg_h<1><<<ab, 256>>>((const uint4*)xh, (uint4*)h0, rowptr, colidx, eps1, n);

    // 4) GEMM1  <-- ncu-profiled launch
    dim3 g4(4, mtiles);
    k_gemm_h<true, true><<<g4, 256, GSM_BYTES>>>(h0, w1a, b1a, h1, n, 256, 512);
    k_gemm_h<true, true><<<g4, 256, GSM_BYTES>>>(h1, w1b, b1b, h2, n, 512, 512);

    // Layer 2
    k_agg_h<2><<<ab, 256>>>((const uint4*)h2, (uint4*)g2, rowptr, colidx, eps2, n);
    k_gemm_h<true, true><<<g4, 256, GSM_BYTES>>>(g2, w2a, b2a, h1, n, 512, 512);
    dim3 g2d(2, mtiles);
    k_gemm_h<false, false><<<g2d, 256, GSM_BYTES>>>(h1, w2b, b2b, out, n, 512, 256);
}

// round 15
// speedup vs baseline: 1.0106x; 1.0106x over previous
#include <cuda_runtime.h>
#include <cuda_fp16.h>
#include <cstdint>

// ---------------------------------------------------------------------------
// GIN 2-layer forward on GB300 (sm_103 target - no tcgen05 in toolchain).
// CSR build (parallel scan, cursor scatter, in-block dtype detect) ->
// warp-per-node fp16 gather aggregation (fp32 accum) -> fp16 mma.sync
// m16n8k16 GEMMs: 128x128 CTA, 4 warps @ 64x64 warp tile, ldmatrix,
// 2-stage cp.async (1 sync/chunk), 3 CTAs/SM target, fused bias+ReLU.
// ---------------------------------------------------------------------------

#define N_MAX 100000
#define E_MAX 1600000

__device__ int    g_rowptr[N_MAX + 1];
__device__ int    g_cur[N_MAX];
__device__ int    g_colidx[E_MAX];
__device__ int    g_cnt[N_MAX];
__device__ int    g_bsum[128];
__device__ __half g_xh[(size_t)N_MAX * 256];
__device__ __half g_h0[(size_t)N_MAX * 256];
__device__ __half g_h1[(size_t)N_MAX * 512];
__device__ __half g_h2[(size_t)N_MAX * 512];
__device__ __half g_g2[(size_t)N_MAX * 512];
// weights transposed to [N][K], fp16
__device__ __half g_w1a[512 * 256];
__device__ __half g_w1b[512 * 512];
__device__ __half g_w2a[512 * 512];
__device__ __half g_w2b[256 * 512];

// ------------------------------- helpers -----------------------------------

__device__ __forceinline__ uint32_t smem_u32(const void* p) {
    uint32_t a;
    asm("{ .reg .u64 t; cvta.to.shared.u64 t, %1; cvt.u32.u64 %0, t; }"
        : "=r"(a) : "l"(p));
    return a;
}
__device__ __forceinline__ void cp16(uint32_t dst, const void* src, int srcsize) {
    asm volatile("cp.async.cg.shared.global [%0], [%1], 16, %2;"
                 :: "r"(dst), "l"(src), "r"(srcsize) : "memory");
}
#define CP_COMMIT() asm volatile("cp.async.commit_group;" ::: "memory")
#define CP_WAIT(n)  asm volatile("cp.async.wait_group %0;" :: "n"(n) : "memory")

__device__ __forceinline__ void mma_f16(float c[4], const uint32_t a[4],
                                        const uint32_t b0, const uint32_t b1) {
    asm volatile(
        "mma.sync.aligned.m16n8k16.row.col.f32.f16.f16.f32 "
        "{%0,%1,%2,%3}, {%4,%5,%6,%7}, {%8,%9}, {%0,%1,%2,%3};"
        : "+f"(c[0]), "+f"(c[1]), "+f"(c[2]), "+f"(c[3])
        : "r"(a[0]), "r"(a[1]), "r"(a[2]), "r"(a[3]), "r"(b0), "r"(b1));
}
__device__ __forceinline__ void ldsm4(uint32_t r[4], uint32_t addr) {
    asm volatile("ldmatrix.sync.aligned.m8n8.x4.shared.b16 {%0,%1,%2,%3}, [%4];"
                 : "=r"(r[0]), "=r"(r[1]), "=r"(r[2]), "=r"(r[3]) : "r"(addr));
}

// Per-block int64-layout detection: all blocks sample the same 256 odd words
// (deterministic, L2-hot). int64 little-endian with values < n  =>  all zero.
__device__ __forceinline__ int detect_is64(const int* __restrict__ ei32) {
    int p = (ei32[2 * (threadIdx.x & 255) + 1] != 0);
    return __syncthreads_or(p) ? 0 : 1;
}

// --------------------------------- CSR --------------------------------------

__global__ void k_count(const int* __restrict__ ei32, int E, int n,
                        int* __restrict__ cnt) {
    int is64 = detect_is64(ei32);
    int e = blockIdx.x * blockDim.x + threadIdx.x;
    if (e >= E) return;
    int d = is64 ? ei32[2 * E + 2 * e] : ei32[E + e];
    if (d < 0) d = 0; if (d >= n) d = n - 1;
    atomicAdd(&cnt[d], 1);
}

__global__ void k_bsum(const int* __restrict__ cnt, int n, int* __restrict__ bsum) {
    __shared__ int sh[256];
    int b = blockIdx.x, t = threadIdx.x;
    int base = b * 1024;
    int s = 0;
#pragma unroll
    for (int q = 0; q < 4; q++) {
        int idx = base + q * 256 + t;
        if (idx < n) s += cnt[idx];
    }
    sh[t] = s;
    __syncthreads();
    for (int off = 128; off > 0; off >>= 1) {
        if (t < off) sh[t] += sh[t + off];
        __syncthreads();
    }
    if (t == 0) bsum[b] = sh[0];
}

__global__ void k_btop(int* __restrict__ bsum, int nb, int* __restrict__ rowptr, int n) {
    __shared__ int sh[128];
    int t = threadIdx.x;
    int v = (t < nb) ? bsum[t] : 0;
    sh[t] = v;
    __syncthreads();
    for (int off = 1; off < 128; off <<= 1) {
        int u = 0;
        if (t >= off) u = sh[t - off];
        __syncthreads();
        if (t >= off) sh[t] += u;
        __syncthreads();
    }
    if (t < nb) bsum[t] = sh[t] - v;
    if (t == 127) rowptr[n] = sh[127];
}

__global__ void k_scanw(const int* __restrict__ cnt, int n,
                        const int* __restrict__ bsum, int* __restrict__ rowptr,
                        int* __restrict__ cur) {
    __shared__ int sh[256];
    int b = blockIdx.x, t = threadIdx.x;
    int base = b * 1024 + t * 4;
    int v[4];
#pragma unroll
    for (int q = 0; q < 4; q++) v[q] = (base + q < n) ? cnt[base + q] : 0;
    int ts = v[0] + v[1] + v[2] + v[3];
    sh[t] = ts;
    __syncthreads();
    for (int off = 1; off < 256; off <<= 1) {
        int u = 0;
        if (t >= off) u = sh[t - off];
        __syncthreads();
        if (t >= off) sh[t] += u;
        __syncthreads();
    }
    int run = sh[t] - ts + bsum[b];
#pragma unroll
    for (int q = 0; q < 4; q++) {
        if (base + q < n) { rowptr[base + q] = run; cur[base + q] = run; }
        run += v[q];
    }
}

__global__ void k_scatter(const int* __restrict__ ei32, int E, int n,
                          int* __restrict__ cur, int* __restrict__ colidx) {
    int is64 = detect_is64(ei32);
    int e = blockIdx.x * blockDim.x + threadIdx.x;
    if (e >= E) return;
    int s, d;
    if (is64) {
        s = ei32[2 * e];
        d = ei32[2 * E + 2 * e];
    } else {
        s = ei32[e];
        d = ei32[E + e];
    }
    if (s < 0) s = 0; if (s >= n) s = n - 1;
    if (d < 0) d = 0; if (d >= n) d = n - 1;
    int pos = atomicAdd(&cur[d], 1);
    if (pos >= 0 && pos < E) colidx[pos] = s;
}

// ------------------------------- conversions -------------------------------
// x -> fp16 (also zeroes cnt[] for the CSR count that follows in stream order)

__global__ void k_cvt_h(const float4* __restrict__ X, __half2* __restrict__ Y,
                        int n4, int* __restrict__ cnt, int n) {
    int i = blockIdx.x * blockDim.x + threadIdx.x;
    if (i < n) cnt[i] = 0;
    if (i < n4) {
        float4 v = X[i];
        Y[2 * i] = __floats2half2_rn(v.x, v.y);
        Y[2 * i + 1] = __floats2half2_rn(v.z, v.w);
    }
}

// all 4 weight transposes in one launch; blockIdx.z selects the matrix
__global__ void k_wt_all(const float* __restrict__ W1a, const float* __restrict__ W1b,
                         const float* __restrict__ W2a, const float* __restrict__ W2b,
                         __half* __restrict__ o1a, __half* __restrict__ o1b,
                         __half* __restrict__ o2a, __half* __restrict__ o2b) {
    __shared__ float t[32][33];
    int z = blockIdx.z;
    const float* W;
    __half* Wt;
    int K, N;
    if (z == 0)      { W = W1a; Wt = o1a; K = 256; N = 512; }
    else if (z == 1) { W = W1b; Wt = o1b; K = 512; N = 512; }
    else if (z == 2) { W = W2a; Wt = o2a; K = 512; N = 512; }
    else             { W = W2b; Wt = o2b; K = 512; N = 256; }
    int k0 = blockIdx.y * 32, n0 = blockIdx.x * 32;
    if (k0 >= K || n0 >= N) return;
    int tx = threadIdx.x, ty = threadIdx.y;
#pragma unroll
    for (int r = ty; r < 32; r += 8)
        t[r][tx] = W[(size_t)(k0 + r) * N + n0 + tx];
    __syncthreads();
#pragma unroll
    for (int r = ty; r < 32; r += 8)
        Wt[(size_t)(n0 + r) * K + k0 + tx] = __float2half_rn(t[tx][r]);
}

// ------------------------------ aggregation -------------------------------
// Warp per node. Lane holds U4 uint4 (8 halfs each). fp32 accumulation,
// fp16 output. U4=1 -> F=256, U4=2 -> F=512. 3-edge unrolled gather.

template <int U4>
__global__ void __launch_bounds__(256)
k_agg_h(const uint4* __restrict__ X, uint4* __restrict__ Y,
        const int* __restrict__ rowptr, const int* __restrict__ colidx,
        const float* __restrict__ epsp, int n) {
    int warp = (blockIdx.x * blockDim.x + threadIdx.x) >> 5;
    if (warp >= n) return;
    int lane = threadIdx.x & 31;
    float sc = 1.0f + epsp[0];
    const int rowU = 32 * U4;
    size_t base = (size_t)warp * rowU + lane;

    float acc[U4][8];
#pragma unroll
    for (int u = 0; u < U4; u++) {
        uint4 v = __ldg(&X[base + u * 32]);
        const __half2* hp = (const __half2*)&v;
#pragma unroll
        for (int q = 0; q < 4; q++) {
            float2 f = __half22float2(hp[q]);
            acc[u][2 * q] = sc * f.x;
            acc[u][2 * q + 1] = sc * f.y;
        }
    }

    int beg = rowptr[warp];
    int end = rowptr[warp + 1];
    int j = beg;
    for (; j + 2 < end; j += 3) {
        int r0 = __ldg(&colidx[j]);
        int r1 = __ldg(&colidx[j + 1]);
        int r2 = __ldg(&colidx[j + 2]);
#pragma unroll
        for (int u = 0; u < U4; u++) {
            uint4 v0 = __ldg(&X[(size_t)r0 * rowU + lane + u * 32]);
            uint4 v1 = __ldg(&X[(size_t)r1 * rowU + lane + u * 32]);
            uint4 v2 = __ldg(&X[(size_t)r2 * rowU + lane + u * 32]);
            const __half2* h0 = (const __half2*)&v0;
            const __half2* h1 = (const __half2*)&v1;
            const __half2* h2 = (const __half2*)&v2;
#pragma unroll
            for (int q = 0; q < 4; q++) {
                float2 f0 = __half22float2(h0[q]);
                float2 f1 = __half22float2(h1[q]);
                float2 f2 = __half22float2(h2[q]);
                acc[u][2 * q] += f0.x + f1.x + f2.x;
                acc[u][2 * q + 1] += f0.y + f1.y + f2.y;
            }
        }
    }
    for (; j < end; j++) {
        int r0 = __ldg(&colidx[j]);
#pragma unroll
        for (int u = 0; u < U4; u++) {
            uint4 v0 = __ldg(&X[(size_t)r0 * rowU + lane + u * 32]);
            const __half2* h0 = (const __half2*)&v0;
#pragma unroll
            for (int q = 0; q < 4; q++) {
                float2 f0 = __half22float2(h0[q]);
                acc[u][2 * q] += f0.x;
                acc[u][2 * q + 1] += f0.y;
            }
        }
    }

#pragma unroll
    for (int u = 0; u < U4; u++) {
        uint4 o;
        __half2* op = (__half2*)&o;
#pragma unroll
        for (int q = 0; q < 4; q++)
            op[q] = __floats2half2_rn(acc[u][2 * q], acc[u][2 * q + 1]);
        Y[base + u * 32] = o;
    }
}

// --------------------------- fp16 mma.sync GEMM ----------------------------
// C = act(A[M,K] @ Wt[N,K]^T + bias). BM=BN=128, BK=64, 128 threads =
// 4 warps (2x2), warp tile 64x64, mma m16n8k16, ldmatrix.x4 (JIT b-frags).
// 2-stage cp.async, ONE sync/chunk (ISSUE after sync is WAR-safe), 3 CTAs/SM.
// smem A: [m][k] halfs stride 72; smem B: [n][k] halfs stride 72.

#define A_B 18432
#define STG_B 36864              // A 18432 + B 18432
#define GSM_BYTES (2 * STG_B)    // 73728 -> 3 CTAs/SM

template <bool RELU, bool OUTH>
__global__ void __launch_bounds__(128, 3)
k_gemm_h(const __half* __restrict__ A, const __half* __restrict__ B,
         const float* __restrict__ bias, void* __restrict__ Cv,
         int M, int K, int N) {
    extern __shared__ __align__(16) char smem[];
    const uint32_t sb = smem_u32(smem);

    const int tid = threadIdx.x;
    const int lane = tid & 31;
    const int w = tid >> 5;
    const int gid = lane >> 2;
    const int tig = lane & 3;
    const int wr = (w >> 1) * 64;   // 0 or 64
    const int wc = (w & 1) * 64;    // 0 or 64
    const int blockRow = blockIdx.y * 128;
    const int blockCol = blockIdx.x * 128;
    const int nch = K >> 6;

    const int quad = lane >> 3;
    const int qr = lane & 7;
    uint32_t aoff[4], boff[4];
#pragma unroll
    for (int ii = 0; ii < 4; ii++)
        aoff[ii] = ((wr + ii * 16 + (quad & 1) * 8 + qr) * 72 + (quad >> 1) * 8) * 2;
#pragma unroll
    for (int jp = 0; jp < 4; jp++)
        boff[jp] = ((wc + jp * 16 + (quad >> 1) * 8 + qr) * 72 + (quad & 1) * 8) * 2
                   + A_B;

    float c[4][8][4];
#pragma unroll
    for (int i = 0; i < 4; i++)
#pragma unroll
        for (int j = 0; j < 8; j++)
#pragma unroll
            for (int q = 0; q < 4; q++) c[i][j][q] = 0.0f;

#define ISSUE(ci, bf)                                                          \
    {                                                                          \
        uint32_t pa = sb + (bf) * STG_B;                                       \
        uint32_t pb = pa + A_B;                                                \
        int KT = (ci) << 6;                                                    \
        _Pragma("unroll") for (int t = 0; t < 8; t++) {                        \
            int cidx = tid + t * 128;                                          \
            int row = cidx >> 3, q = cidx & 7;                                 \
            int grow = blockRow + row;                                         \
            cp16(pa + row * 144 + q * 16,                                      \
                 &A[(size_t)grow * K + KT + q * 8], grow < M ? 16 : 0);        \
        }                                                                      \
        _Pragma("unroll") for (int t = 0; t < 8; t++) {                        \
            int cidx = tid + t * 128;                                          \
            int row = cidx >> 3, q = cidx & 7;                                 \
            cp16(pb + row * 144 + q * 16,                                      \
                 &B[(size_t)(blockCol + row) * K + KT + q * 8], 16);           \
        }                                                                      \
        CP_COMMIT();                                                           \
    }

    ISSUE(0, 0);

    for (int i = 0; i < nch; i++) {
        CP_WAIT(0);
        __syncthreads();   // data ready AND all warps past compute(i-1)
        if (i + 1 < nch) ISSUE(i + 1, (i + 1) & 1);  // overlaps compute(i)

        uint32_t base = sb + (i & 1) * STG_B;
#pragma unroll
        for (int ks = 0; ks < 4; ks++) {
            uint32_t kboff = ks * 32;  // 16 halfs
            uint32_t a[4][4];
#pragma unroll
            for (int ii = 0; ii < 4; ii++) ldsm4(a[ii], base + aoff[ii] + kboff);
#pragma unroll
            for (int jp = 0; jp < 4; jp++) {
                uint32_t b[4];
                ldsm4(b, base + boff[jp] + kboff);
#pragma unroll
                for (int ii = 0; ii < 4; ii++) {
                    mma_f16(c[ii][2 * jp], a[ii], b[0], b[1]);
                    mma_f16(c[ii][2 * jp + 1], a[ii], b[2], b[3]);
                }
            }
        }
    }

    // epilogue
#pragma unroll
    for (int j = 0; j < 8; j++) {
        int n0 = blockCol + wc + j * 8 + 2 * tig;
        float bb0 = bias[n0];
        float bb1 = bias[n0 + 1];
#pragma unroll
        for (int i = 0; i < 4; i++) {
            int m = blockRow + wr + i * 16 + gid;
            float v0 = c[i][j][0] + bb0;
            float v1 = c[i][j][1] + bb1;
            float v2 = c[i][j][2] + bb0;
            float v3 = c[i][j][3] + bb1;
            if (RELU) {
                v0 = fmaxf(v0, 0.f); v1 = fmaxf(v1, 0.f);
                v2 = fmaxf(v2, 0.f); v3 = fmaxf(v3, 0.f);
            }
            if (OUTH) {
                __half2* Ch = (__half2*)Cv;
                if (m < M) Ch[(size_t)m * (N >> 1) + (n0 >> 1)] = __floats2half2_rn(v0, v1);
                if (m + 8 < M)
                    Ch[(size_t)(m + 8) * (N >> 1) + (n0 >> 1)] = __floats2half2_rn(v2, v3);
            } else {
                float* Cf = (float*)Cv;
                if (m < M) *(float2*)&Cf[(size_t)m * N + n0] = make_float2(v0, v1);
                if (m + 8 < M)
                    *(float2*)&Cf[(size_t)(m + 8) * N + n0] = make_float2(v2, v3);
            }
        }
    }
#undef ISSUE
}

// ------------------------------ launcher -----------------------------------

extern "C" void kernel_launch(void* const* d_in, const int* in_sizes, int n_in,
                              void* d_out, int out_size) {
    const float* x    = (const float*)d_in[0];
    const int*   ei   = (const int*)d_in[1];
    const float* W1a  = (const float*)d_in[2];
    const float* b1a  = (const float*)d_in[3];
    const float* W1b  = (const float*)d_in[4];
    const float* b1b  = (const float*)d_in[5];
    const float* W2a  = (const float*)d_in[6];
    const float* b2a  = (const float*)d_in[7];
    const float* W2b  = (const float*)d_in[8];
    const float* b2b  = (const float*)d_in[9];
    const float* eps1 = (const float*)d_in[10];
    const float* eps2 = (const float*)d_in[11];
    float*       out  = (float*)d_out;

    int n = in_sizes[0] / 256;  // 100000 nodes
    int E = in_sizes[1] / 2;    // 1600000 edges

    int *rowptr, *cur, *colidx, *cnt, *bsum;
    __half *xh, *h0, *h1, *h2, *g2, *w1a, *w1b, *w2a, *w2b;
    cudaGetSymbolAddress((void**)&rowptr, g_rowptr);
    cudaGetSymbolAddress((void**)&cur, g_cur);
    cudaGetSymbolAddress((void**)&colidx, g_colidx);
    cudaGetSymbolAddress((void**)&cnt, g_cnt);
    cudaGetSymbolAddress((void**)&bsum, g_bsum);
    cudaGetSymbolAddress((void**)&xh, g_xh);
    cudaGetSymbolAddress((void**)&h0, g_h0);
    cudaGetSymbolAddress((void**)&h1, g_h1);
    cudaGetSymbolAddress((void**)&h2, g_h2);
    cudaGetSymbolAddress((void**)&g2, g_g2);
    cudaGetSymbolAddress((void**)&w1a, g_w1a);
    cudaGetSymbolAddress((void**)&w1b, g_w1b);
    cudaGetSymbolAddress((void**)&w2a, g_w2a);
    cudaGetSymbolAddress((void**)&w2b, g_w2b);

    cudaFuncSetAttribute(k_gemm_h<true, true>,
                         cudaFuncAttributeMaxDynamicSharedMemorySize, GSM_BYTES);
    cudaFuncSetAttribute(k_gemm_h<false, false>,
                         cudaFuncAttributeMaxDynamicSharedMemorySize, GSM_BYTES);

    int eb = (E + 255) / 256;
    int nb = (n + 1023) / 1024;

    // conversions (x -> fp16 + cnt zeroing; all 4 weight transposes fused)
    k_cvt_h<<<(n * 64 + 255) / 256, 256>>>((const float4*)x, (__half2*)xh,
                                           n * 64, cnt, n);
    k_wt_all<<<dim3(16, 16, 4), dim3(32, 8)>>>(W1a, W1b, W2a, W2b,
                                               w1a, w1b, w2a, w2b);

    // CSR build (per-block dtype detect, cursor-based scatter)
    k_count<<<eb, 256>>>(ei, E, n, cnt);
    k_bsum<<<nb, 256>>>(cnt, n, bsum);
    k_btop<<<1, 128>>>(bsum, nb, rowptr, n);
    k_scanw<<<nb, 256>>>(cnt, n, bsum, rowptr, cur);
    k_scatter<<<eb, 256>>>(ei, E, n, cur, colidx);

    int mtiles = (n + 127) / 128;
    int ab = (n + 7) / 8;

    // Layer 1
    k_agg_h<1><<<ab, 256>>>((const uint4*)xh, (uint4*)h0, rowptr, colidx, eps1, n);
    dim3 g4(4, mtiles);
    k_gemm_h<true, true><<<g4, 128, GSM_BYTES>>>(h0, w1a, b1a, h1, n, 256, 512);
    k_gemm_h<true, true><<<g4, 128, GSM_BYTES>>>(h1, w1b, b1b, h2, n, 512, 512);

    // Layer 2
    k_agg_h<2><<<ab, 256>>>((const uint4*)h2, (uint4*)g2, rowptr, colidx, eps2, n);
    k_gemm_h<true, true><<<g4, 128, GSM_BYTES>>>(g2, w2a, b2a, h1, n, 512, 512);
    dim3 g2d(2, mtiles);
    k_gemm_h<false, false><<<g2d, 128, GSM_BYTES>>>(h1, w2b, b2b, out, n, 512, 256);
}

// round 16
// speedup vs baseline: 1.0525x; 1.0414x over previous
#include <cuda_runtime.h>
#include <cuda_fp16.h>
#include <cstdint>

// ---------------------------------------------------------------------------
// GIN 2-layer forward on GB300 (sm_103 target - no tcgen05 in toolchain).
// CSR build (parallel scan, cursor scatter, in-block dtype detect) ->
// warp-per-node fp16 gather aggregation (fp32 accum) -> fp16 mma.sync
// m16n8k16 GEMMs: 128x128 CTA, 4 warps @ 64x64 warp tile, ldmatrix,
// 2-stage cp.async (1 sync/chunk), 3 CTAs/SM, register-trimmed (<=170),
// fused bias+ReLU.
// ---------------------------------------------------------------------------

#define N_MAX 100000
#define E_MAX 1600000

__device__ int    g_rowptr[N_MAX + 1];
__device__ int    g_cur[N_MAX];
__device__ int    g_colidx[E_MAX];
__device__ int    g_cnt[N_MAX];
__device__ int    g_bsum[128];
__device__ __half g_xh[(size_t)N_MAX * 256];
__device__ __half g_h0[(size_t)N_MAX * 256];
__device__ __half g_h1[(size_t)N_MAX * 512];
__device__ __half g_h2[(size_t)N_MAX * 512];
__device__ __half g_g2[(size_t)N_MAX * 512];
// weights transposed to [N][K], fp16
__device__ __half g_w1a[512 * 256];
__device__ __half g_w1b[512 * 512];
__device__ __half g_w2a[512 * 512];
__device__ __half g_w2b[256 * 512];

// ------------------------------- helpers -----------------------------------

__device__ __forceinline__ uint32_t smem_u32(const void* p) {
    uint32_t a;
    asm("{ .reg .u64 t; cvta.to.shared.u64 t, %1; cvt.u32.u64 %0, t; }"
        : "=r"(a) : "l"(p));
    return a;
}
__device__ __forceinline__ void cp16(uint32_t dst, const void* src, int srcsize) {
    asm volatile("cp.async.cg.shared.global [%0], [%1], 16, %2;"
                 :: "r"(dst), "l"(src), "r"(srcsize) : "memory");
}
#define CP_COMMIT() asm volatile("cp.async.commit_group;" ::: "memory")
#define CP_WAIT(n)  asm volatile("cp.async.wait_group %0;" :: "n"(n) : "memory")

__device__ __forceinline__ void mma_f16(float c[4], const uint32_t a[4],
                                        const uint32_t b0, const uint32_t b1) {
    asm volatile(
        "mma.sync.aligned.m16n8k16.row.col.f32.f16.f16.f32 "
        "{%0,%1,%2,%3}, {%4,%5,%6,%7}, {%8,%9}, {%0,%1,%2,%3};"
        : "+f"(c[0]), "+f"(c[1]), "+f"(c[2]), "+f"(c[3])
        : "r"(a[0]), "r"(a[1]), "r"(a[2]), "r"(a[3]), "r"(b0), "r"(b1));
}
__device__ __forceinline__ void ldsm4(uint32_t r[4], uint32_t addr) {
    asm volatile("ldmatrix.sync.aligned.m8n8.x4.shared.b16 {%0,%1,%2,%3}, [%4];"
                 : "=r"(r[0]), "=r"(r[1]), "=r"(r[2]), "=r"(r[3]) : "r"(addr));
}

// Per-block int64-layout detection: all blocks sample the same 256 odd words
// (deterministic, L2-hot). int64 little-endian with values < n  =>  all zero.
__device__ __forceinline__ int detect_is64(const int* __restrict__ ei32) {
    int p = (ei32[2 * (threadIdx.x & 255) + 1] != 0);
    return __syncthreads_or(p) ? 0 : 1;
}

// --------------------------------- CSR --------------------------------------

__global__ void k_count(const int* __restrict__ ei32, int E, int n,
                        int* __restrict__ cnt) {
    int is64 = detect_is64(ei32);
    int e = blockIdx.x * blockDim.x + threadIdx.x;
    if (e >= E) return;
    int d = is64 ? ei32[2 * E + 2 * e] : ei32[E + e];
    if (d < 0) d = 0; if (d >= n) d = n - 1;
    atomicAdd(&cnt[d], 1);
}

__global__ void k_bsum(const int* __restrict__ cnt, int n, int* __restrict__ bsum) {
    __shared__ int sh[256];
    int b = blockIdx.x, t = threadIdx.x;
    int base = b * 1024;
    int s = 0;
#pragma unroll
    for (int q = 0; q < 4; q++) {
        int idx = base + q * 256 + t;
        if (idx < n) s += cnt[idx];
    }
    sh[t] = s;
    __syncthreads();
    for (int off = 128; off > 0; off >>= 1) {
        if (t < off) sh[t] += sh[t + off];
        __syncthreads();
    }
    if (t == 0) bsum[b] = sh[0];
}

__global__ void k_btop(int* __restrict__ bsum, int nb, int* __restrict__ rowptr, int n) {
    __shared__ int sh[128];
    int t = threadIdx.x;
    int v = (t < nb) ? bsum[t] : 0;
    sh[t] = v;
    __syncthreads();
    for (int off = 1; off < 128; off <<= 1) {
        int u = 0;
        if (t >= off) u = sh[t - off];
        __syncthreads();
        if (t >= off) sh[t] += u;
        __syncthreads();
    }
    if (t < nb) bsum[t] = sh[t] - v;
    if (t == 127) rowptr[n] = sh[127];
}

__global__ void k_scanw(const int* __restrict__ cnt, int n,
                        const int* __restrict__ bsum, int* __restrict__ rowptr,
                        int* __restrict__ cur) {
    __shared__ int sh[256];
    int b = blockIdx.x, t = threadIdx.x;
    int base = b * 1024 + t * 4;
    int v[4];
#pragma unroll
    for (int q = 0; q < 4; q++) v[q] = (base + q < n) ? cnt[base + q] : 0;
    int ts = v[0] + v[1] + v[2] + v[3];
    sh[t] = ts;
    __syncthreads();
    for (int off = 1; off < 256; off <<= 1) {
        int u = 0;
        if (t >= off) u = sh[t - off];
        __syncthreads();
        if (t >= off) sh[t] += u;
        __syncthreads();
    }
    int run = sh[t] - ts + bsum[b];
#pragma unroll
    for (int q = 0; q < 4; q++) {
        if (base + q < n) { rowptr[base + q] = run; cur[base + q] = run; }
        run += v[q];
    }
}

__global__ void k_scatter(const int* __restrict__ ei32, int E, int n,
                          int* __restrict__ cur, int* __restrict__ colidx) {
    int is64 = detect_is64(ei32);
    int e = blockIdx.x * blockDim.x + threadIdx.x;
    if (e >= E) return;
    int s, d;
    if (is64) {
        s = ei32[2 * e];
        d = ei32[2 * E + 2 * e];
    } else {
        s = ei32[e];
        d = ei32[E + e];
    }
    if (s < 0) s = 0; if (s >= n) s = n - 1;
    if (d < 0) d = 0; if (d >= n) d = n - 1;
    int pos = atomicAdd(&cur[d], 1);
    if (pos >= 0 && pos < E) colidx[pos] = s;
}

// ------------------------------- conversions -------------------------------
// x -> fp16 (also zeroes cnt[] for the CSR count that follows in stream order)

__global__ void k_cvt_h(const float4* __restrict__ X, __half2* __restrict__ Y,
                        int n4, int* __restrict__ cnt, int n) {
    int i = blockIdx.x * blockDim.x + threadIdx.x;
    if (i < n) cnt[i] = 0;
    if (i < n4) {
        float4 v = X[i];
        Y[2 * i] = __floats2half2_rn(v.x, v.y);
        Y[2 * i + 1] = __floats2half2_rn(v.z, v.w);
    }
}

// all 4 weight transposes in one launch; blockIdx.z selects the matrix
__global__ void k_wt_all(const float* __restrict__ W1a, const float* __restrict__ W1b,
                         const float* __restrict__ W2a, const float* __restrict__ W2b,
                         __half* __restrict__ o1a, __half* __restrict__ o1b,
                         __half* __restrict__ o2a, __half* __restrict__ o2b) {
    __shared__ float t[32][33];
    int z = blockIdx.z;
    const float* W;
    __half* Wt;
    int K, N;
    if (z == 0)      { W = W1a; Wt = o1a; K = 256; N = 512; }
    else if (z == 1) { W = W1b; Wt = o1b; K = 512; N = 512; }
    else if (z == 2) { W = W2a; Wt = o2a; K = 512; N = 512; }
    else             { W = W2b; Wt = o2b; K = 512; N = 256; }
    int k0 = blockIdx.y * 32, n0 = blockIdx.x * 32;
    if (k0 >= K || n0 >= N) return;
    int tx = threadIdx.x, ty = threadIdx.y;
#pragma unroll
    for (int r = ty; r < 32; r += 8)
        t[r][tx] = W[(size_t)(k0 + r) * N + n0 + tx];
    __syncthreads();
#pragma unroll
    for (int r = ty; r < 32; r += 8)
        Wt[(size_t)(n0 + r) * K + k0 + tx] = __float2half_rn(t[tx][r]);
}

// ------------------------------ aggregation -------------------------------
// Warp per node. Lane holds U4 uint4 (8 halfs each). fp32 accumulation,
// fp16 output. U4=1 -> F=256, U4=2 -> F=512. 3-edge unrolled gather.

template <int U4>
__global__ void __launch_bounds__(256)
k_agg_h(const uint4* __restrict__ X, uint4* __restrict__ Y,
        const int* __restrict__ rowptr, const int* __restrict__ colidx,
        const float* __restrict__ epsp, int n) {
    int warp = (blockIdx.x * blockDim.x + threadIdx.x) >> 5;
    if (warp >= n) return;
    int lane = threadIdx.x & 31;
    float sc = 1.0f + epsp[0];
    const int rowU = 32 * U4;
    size_t base = (size_t)warp * rowU + lane;

    float acc[U4][8];
#pragma unroll
    for (int u = 0; u < U4; u++) {
        uint4 v = __ldg(&X[base + u * 32]);
        const __half2* hp = (const __half2*)&v;
#pragma unroll
        for (int q = 0; q < 4; q++) {
            float2 f = __half22float2(hp[q]);
            acc[u][2 * q] = sc * f.x;
            acc[u][2 * q + 1] = sc * f.y;
        }
    }

    int beg = rowptr[warp];
    int end = rowptr[warp + 1];
    int j = beg;
    for (; j + 2 < end; j += 3) {
        int r0 = __ldg(&colidx[j]);
        int r1 = __ldg(&colidx[j + 1]);
        int r2 = __ldg(&colidx[j + 2]);
#pragma unroll
        for (int u = 0; u < U4; u++) {
            uint4 v0 = __ldg(&X[(size_t)r0 * rowU + lane + u * 32]);
            uint4 v1 = __ldg(&X[(size_t)r1 * rowU + lane + u * 32]);
            uint4 v2 = __ldg(&X[(size_t)r2 * rowU + lane + u * 32]);
            const __half2* h0 = (const __half2*)&v0;
            const __half2* h1 = (const __half2*)&v1;
            const __half2* h2 = (const __half2*)&v2;
#pragma unroll
            for (int q = 0; q < 4; q++) {
                float2 f0 = __half22float2(h0[q]);
                float2 f1 = __half22float2(h1[q]);
                float2 f2 = __half22float2(h2[q]);
                acc[u][2 * q] += f0.x + f1.x + f2.x;
                acc[u][2 * q + 1] += f0.y + f1.y + f2.y;
            }
        }
    }
    for (; j < end; j++) {
        int r0 = __ldg(&colidx[j]);
#pragma unroll
        for (int u = 0; u < U4; u++) {
            uint4 v0 = __ldg(&X[(size_t)r0 * rowU + lane + u * 32]);
            const __half2* h0 = (const __half2*)&v0;
#pragma unroll
            for (int q = 0; q < 4; q++) {
                float2 f0 = __half22float2(h0[q]);
                acc[u][2 * q] += f0.x;
                acc[u][2 * q + 1] += f0.y;
            }
        }
    }

#pragma unroll
    for (int u = 0; u < U4; u++) {
        uint4 o;
        __half2* op = (__half2*)&o;
#pragma unroll
        for (int q = 0; q < 4; q++)
            op[q] = __floats2half2_rn(acc[u][2 * q], acc[u][2 * q + 1]);
        Y[base + u * 32] = o;
    }
}

// --------------------------- fp16 mma.sync GEMM ----------------------------
// C = act(A[M,K] @ Wt[N,K]^T + bias). BM=BN=128, BK=64, 128 threads =
// 4 warps (2x2), warp tile 64x64, mma m16n8k16, ldmatrix.x4 (JIT b-frags).
// 2-stage cp.async, ONE sync/chunk, 3 CTAs/SM, register-trimmed:
// affine fragment offsets (base + ii*2304), hoisted global pointers.
// smem A: [m][k] halfs stride 72; smem B: [n][k] halfs stride 72.

#define A_B 18432
#define STG_B 36864              // A 18432 + B 18432
#define GSM_BYTES (2 * STG_B)    // 73728 -> 3 CTAs/SM

template <bool RELU, bool OUTH>
__global__ void __launch_bounds__(128, 3)
k_gemm_h(const __half* __restrict__ A, const __half* __restrict__ B,
         const float* __restrict__ bias, void* __restrict__ Cv,
         int M, int K, int N) {
    extern __shared__ __align__(16) char smem[];
    const uint32_t sb = smem_u32(smem);

    const int tid = threadIdx.x;
    const int lane = tid & 31;
    const int w = tid >> 5;
    const int gid = lane >> 2;
    const int tig = lane & 3;
    const int wr = (w >> 1) * 64;   // 0 or 64
    const int wc = (w & 1) * 64;    // 0 or 64
    const int blockRow = blockIdx.y * 128;
    const int blockCol = blockIdx.x * 128;
    const int nch = K >> 6;

    const int quad = lane >> 3;
    const int qr = lane & 7;
    // affine fragment offset bases (step per ii/jp = 16*72*2 = 2304 bytes)
    const uint32_t aoff0 = sb +
        ((wr + (quad & 1) * 8 + qr) * 72 + (quad >> 1) * 8) * 2;
    const uint32_t boff0 = sb + A_B +
        ((wc + (quad >> 1) * 8 + qr) * 72 + (quad & 1) * 8) * 2;

    // hoisted per-thread global pointers for cp.async (row/q fixed per t-slot)
    const int ldrow = tid >> 3;          // 0..15 (t adds 16 per slot)
    const int ldq = (tid & 7) * 8;       // half offset within 64-wide chunk
    const __half* Ap = A + (size_t)(blockRow + ldrow) * K + ldq;
    const __half* Bp = B + (size_t)(blockCol + ldrow) * K + ldq;
    const uint32_t sA0 = sb + ldrow * 144 + (ldq * 2);
    const uint32_t sB0 = sA0 + A_B;
    const bool arowv0 = (blockRow + ldrow) < M;   // per-slot validity handled below

    float c[4][8][4];
#pragma unroll
    for (int i = 0; i < 4; i++)
#pragma unroll
        for (int j = 0; j < 8; j++)
#pragma unroll
            for (int q = 0; q < 4; q++) c[i][j][q] = 0.0f;

#define ISSUE(ci, bf)                                                          \
    {                                                                          \
        uint32_t so = (bf) * STG_B;                                            \
        int KT = (ci) << 6;                                                    \
        _Pragma("unroll") for (int t = 0; t < 8; t++) {                        \
            int grow = blockRow + ldrow + t * 16;                              \
            cp16(sA0 + so + t * 2304,                                          \
                 Ap + (size_t)t * 16 * K + KT, grow < M ? 16 : 0);             \
        }                                                                      \
        _Pragma("unroll") for (int t = 0; t < 8; t++) {                        \
            cp16(sB0 + so + t * 2304, Bp + (size_t)t * 16 * K + KT, 16);       \
        }                                                                      \
        CP_COMMIT();                                                           \
    }

    ISSUE(0, 0);

    for (int i = 0; i < nch; i++) {
        CP_WAIT(0);
        __syncthreads();   // data ready AND all warps past compute(i-1)
        if (i + 1 < nch) ISSUE(i + 1, (i + 1) & 1);  // overlaps compute(i)

        uint32_t so = (i & 1) * STG_B;
#pragma unroll
        for (int ks = 0; ks < 4; ks++) {
            uint32_t kboff = so + ks * 32;  // 16 halfs
            uint32_t a[4][4];
#pragma unroll
            for (int ii = 0; ii < 4; ii++)
                ldsm4(a[ii], aoff0 + ii * 2304 + kboff);
#pragma unroll
            for (int jp = 0; jp < 4; jp++) {
                uint32_t b[4];
                ldsm4(b, boff0 + jp * 2304 + kboff);
#pragma unroll
                for (int ii = 0; ii < 4; ii++) {
                    mma_f16(c[ii][2 * jp], a[ii], b[0], b[1]);
                    mma_f16(c[ii][2 * jp + 1], a[ii], b[2], b[3]);
                }
            }
        }
    }
    (void)arowv0;

    // epilogue
#pragma unroll
    for (int j = 0; j < 8; j++) {
        int n0 = blockCol + wc + j * 8 + 2 * tig;
        float bb0 = bias[n0];
        float bb1 = bias[n0 + 1];
#pragma unroll
        for (int i = 0; i < 4; i++) {
            int m = blockRow + wr + i * 16 + gid;
            float v0 = c[i][j][0] + bb0;
            float v1 = c[i][j][1] + bb1;
            float v2 = c[i][j][2] + bb0;
            float v3 = c[i][j][3] + bb1;
            if (RELU) {
                v0 = fmaxf(v0, 0.f); v1 = fmaxf(v1, 0.f);
                v2 = fmaxf(v2, 0.f); v3 = fmaxf(v3, 0.f);
            }
            if (OUTH) {
                __half2* Ch = (__half2*)Cv;
                if (m < M) Ch[(size_t)m * (N >> 1) + (n0 >> 1)] = __floats2half2_rn(v0, v1);
                if (m + 8 < M)
                    Ch[(size_t)(m + 8) * (N >> 1) + (n0 >> 1)] = __floats2half2_rn(v2, v3);
            } else {
                float* Cf = (float*)Cv;
                if (m < M) *(float2*)&Cf[(size_t)m * N + n0] = make_float2(v0, v1);
                if (m + 8 < M)
                    *(float2*)&Cf[(size_t)(m + 8) * N + n0] = make_float2(v2, v3);
            }
        }
    }
#undef ISSUE
}

// ------------------------------ launcher -----------------------------------

extern "C" void kernel_launch(void* const* d_in, const int* in_sizes, int n_in,
                              void* d_out, int out_size) {
    const float* x    = (const float*)d_in[0];
    const int*   ei   = (const int*)d_in[1];
    const float* W1a  = (const float*)d_in[2];
    const float* b1a  = (const float*)d_in[3];
    const float* W1b  = (const float*)d_in[4];
    const float* b1b  = (const float*)d_in[5];
    const float* W2a  = (const float*)d_in[6];
    const float* b2a  = (const float*)d_in[7];
    const float* W2b  = (const float*)d_in[8];
    const float* b2b  = (const float*)d_in[9];
    const float* eps1 = (const float*)d_in[10];
    const float* eps2 = (const float*)d_in[11];
    float*       out  = (float*)d_out;

    int n = in_sizes[0] / 256;  // 100000 nodes
    int E = in_sizes[1] / 2;    // 1600000 edges

    int *rowptr, *cur, *colidx, *cnt, *bsum;
    __half *xh, *h0, *h1, *h2, *g2, *w1a, *w1b, *w2a, *w2b;
    cudaGetSymbolAddress((void**)&rowptr, g_rowptr);
    cudaGetSymbolAddress((void**)&cur, g_cur);
    cudaGetSymbolAddress((void**)&colidx, g_colidx);
    cudaGetSymbolAddress((void**)&cnt, g_cnt);
    cudaGetSymbolAddress((void**)&bsum, g_bsum);
    cudaGetSymbolAddress((void**)&xh, g_xh);
    cudaGetSymbolAddress((void**)&h0, g_h0);
    cudaGetSymbolAddress((void**)&h1, g_h1);
    cudaGetSymbolAddress((void**)&h2, g_h2);
    cudaGetSymbolAddress((void**)&g2, g_g2);
    cudaGetSymbolAddress((void**)&w1a, g_w1a);
    cudaGetSymbolAddress((void**)&w1b, g_w1b);
    cudaGetSymbolAddress((void**)&w2a, g_w2a);
    cudaGetSymbolAddress((void**)&w2b, g_w2b);

    cudaFuncSetAttribute(k_gemm_h<true, true>,
                         cudaFuncAttributeMaxDynamicSharedMemorySize, GSM_BYTES);
    cudaFuncSetAttribute(k_gemm_h<false, false>,
                         cudaFuncAttributeMaxDynamicSharedMemorySize, GSM_BYTES);

    int eb = (E + 255) / 256;
    int nb = (n + 1023) / 1024;

    // conversions (x -> fp16 + cnt zeroing; all 4 weight transposes fused)
    k_cvt_h<<<(n * 64 + 255) / 256, 256>>>((const float4*)x, (__half2*)xh,
                                           n * 64, cnt, n);
    k_wt_all<<<dim3(16, 16, 4), dim3(32, 8)>>>(W1a, W1b, W2a, W2b,
                                               w1a, w1b, w2a, w2b);

    // CSR build (per-block dtype detect, cursor-based scatter)
    k_count<<<eb, 256>>>(ei, E, n, cnt);
    k_bsum<<<nb, 256>>>(cnt, n, bsum);
    k_btop<<<1, 128>>>(bsum, nb, rowptr, n);
    k_scanw<<<nb, 256>>>(cnt, n, bsum, rowptr, cur);
    k_scatter<<<eb, 256>>>(ei, E, n, cur, colidx);

    int mtiles = (n + 127) / 128;
    int ab = (n + 7) / 8;

    // Layer 1
    k_agg_h<1><<<ab, 256>>>((const uint4*)xh, (uint4*)h0, rowptr, colidx, eps1, n);
    dim3 g4(4, mtiles);
    k_gemm_h<true, true><<<g4, 128, GSM_BYTES>>>(h0, w1a, b1a, h1, n, 256, 512);
    k_gemm_h<true, true><<<g4, 128, GSM_BYTES>>>(h1, w1b, b1b, h2, n, 512, 512);

    // Layer 2
    k_agg_h<2><<<ab, 256>>>((const uint4*)h2, (uint4*)g2, rowptr, colidx, eps2, n);
    k_gemm_h<true, true><<<g4, 128, GSM_BYTES>>>(g2, w2a, b2a, h1, n, 512, 512);
    dim3 g2d(2, mtiles);
    k_gemm_h<false, false><<<g2d, 128, GSM_BYTES>>>(h1, w2b, b2b, out, n, 512, 256);
}